// round 1
// baseline (speedup 1.0000x reference)
#include <cuda_runtime.h>
#include <cuda_bf16.h>

namespace {

constexpr int Dd = 160;
constexpr int Hh = 192;
constexpr int Ww = 224;
constexpr int HW = Hh * Ww;        // 43008
constexpr int N  = Dd * HW;        // 6881280  (= 26880 * 256 exactly)

__global__ __launch_bounds__(256)
void st3d_kernel(const float* __restrict__ img,   // input1: (160,192,224) fp32
                 const float* __restrict__ off,   // input2: (3,160,192,224) fp32
                 float* __restrict__ out)         // (160,192,224) fp32
{
    const int g = blockIdx.x * 256 + threadIdx.x;   // grid is exact, no tail

    // decode (d, h, w) from linear index; lanes are consecutive in w
    const int w = g % Ww;
    const int t = g / Ww;
    const int h = t % Hh;
    const int d = t / Hh;

    // per-voxel offsets, 3 coalesced channel loads
    const float dDv = __ldg(off + g);
    const float dHv = __ldg(off + N + g);
    const float dWv = __ldg(off + 2 * N + g);

    // padded-space sampling coordinates (reference adds +1 for the pad shift)
    const float Dup = dDv + (float)(d + 1);
    const float Hup = dHv + (float)(h + 1);
    const float Wup = dWv + (float)(w + 1);

    // floor + fractional part (unclipped — clipping only ever hits zero-pad taps)
    const int df = __float2int_rd(Dup);
    const int hf = __float2int_rd(Hup);
    const int wf = __float2int_rd(Wup);

    const float td = Dup - (float)df;   // weight of the "+1" tap along d
    const float th = Hup - (float)hf;
    const float tw = Wup - (float)wf;

    // data-space indices of the floor taps (padded coord - 1)
    const int d0 = df - 1, h0 = hf - 1, w0 = wf - 1;

    // interior validity per side, per dim (unsigned trick covers both ends)
    const bool pd0 = (unsigned)d0 < (unsigned)Dd;   // 1 <= df  <= D
    const bool pd1 = (unsigned)df < (unsigned)Dd;   // 1 <= df+1<= D
    const bool ph0 = (unsigned)h0 < (unsigned)Hh;
    const bool ph1 = (unsigned)hf < (unsigned)Hh;
    const bool pw0 = (unsigned)w0 < (unsigned)Ww;
    const bool pw1 = (unsigned)wf < (unsigned)Ww;

    // single base index; all 8 taps are immediate offsets from it
    const int i = d0 * HW + h0 * Ww + w0;

    float v000 = 0.f, v001 = 0.f, v010 = 0.f, v011 = 0.f;
    float v100 = 0.f, v101 = 0.f, v110 = 0.f, v111 = 0.f;

    // predicated loads: off-lanes never touch memory, so wild indices are safe
    if (pd0 & ph0 & pw0) v000 = img[i];
    if (pd0 & ph0 & pw1) v001 = img[i + 1];
    if (pd0 & ph1 & pw0) v010 = img[i + Ww];
    if (pd0 & ph1 & pw1) v011 = img[i + Ww + 1];
    if (pd1 & ph0 & pw0) v100 = img[i + HW];
    if (pd1 & ph0 & pw1) v101 = img[i + HW + 1];
    if (pd1 & ph1 & pw0) v110 = img[i + HW + Ww];
    if (pd1 & ph1 & pw1) v111 = img[i + HW + Ww + 1];

    // trilinear lerp tree: w, then h, then d
    const float a00 = v000 + tw * (v001 - v000);
    const float a01 = v010 + tw * (v011 - v010);
    const float a10 = v100 + tw * (v101 - v100);
    const float a11 = v110 + tw * (v111 - v110);

    const float b0 = a00 + th * (a01 - a00);
    const float b1 = a10 + th * (a11 - a10);

    out[g] = b0 + td * (b1 - b0);
}

} // namespace

extern "C" void kernel_launch(void* const* d_in, const int* in_sizes, int n_in,
                              void* d_out, int out_size)
{
    const float* img = (const float*)d_in[0];   // input1
    const float* off = (const float*)d_in[1];   // input2
    float* out = (float*)d_out;

    st3d_kernel<<<N / 256, 256>>>(img, off, out);
}